// round 1
// baseline (speedup 1.0000x reference)
#include <cuda_runtime.h>
#include <cuda_fp16.h>
#include <math.h>

#define B_  256
#define T_  512
#define S_  64
#define O_  128
#define H_  128
#define G4  512   // 4*H

// ---------------- scratch (device globals; no runtime allocation) ----------
__device__ float  g_gz[(size_t)B_ * T_ * G4];   // 268 MB: obs@K + b
__device__ float  g_hs[(size_t)B_ * T_ * H_];   // 67 MB : LSTM hidden states
__device__ float  g_pm[(size_t)B_ * T_ * S_];   // 33.5MB: posterior mean
__device__ float  g_ps[(size_t)B_ * T_ * S_];   // 33.5MB: posterior scale
__device__ double g_acc[2];                     // [0]=KL sum, [1]=recon-term sum

__device__ __forceinline__ float softplusf_(float x) {
    return fmaxf(x, 0.f) + log1pf(__expf(-fabsf(x)));
}
__device__ __forceinline__ float sigmoidf_(float x) {
    return 1.f / (1.f + __expf(-x));
}

// ---------------------------------------------------------------------------
__global__ void k_zero() {
    if (threadIdx.x < 2) g_acc[threadIdx.x] = 0.0;
}

// ---------------------------------------------------------------------------
// gz[bt, 0:512] = obs[bt, 0:128] @ K[128,512] + b[512]
// grid (4, 2048): x = 128-col block, y = 64-row block.  256 threads.
// smem: AsT[128][68] (A transposed, padded) + Bs[128][128]
__global__ void k_xk(const float* __restrict__ obs, const float* __restrict__ K,
                     const float* __restrict__ bl) {
    extern __shared__ float sm[];
    float* AsT = sm;               // 128*68
    float* Bs  = sm + 128 * 68;    // 128*128
    const int tid = threadIdx.x;
    const int bt0 = blockIdx.y * 64;
    const int c0  = blockIdx.x * 128;

    const float4* obs4 = (const float4*)obs;
    #pragma unroll
    for (int i = tid; i < 64 * 32; i += 256) {
        int row = i >> 5, c4 = i & 31;
        float4 v = obs4[(size_t)(bt0 + row) * 32 + c4];
        AsT[(c4 * 4 + 0) * 68 + row] = v.x;
        AsT[(c4 * 4 + 1) * 68 + row] = v.y;
        AsT[(c4 * 4 + 2) * 68 + row] = v.z;
        AsT[(c4 * 4 + 3) * 68 + row] = v.w;
    }
    #pragma unroll
    for (int i = tid; i < 128 * 32; i += 256) {
        int k = i >> 5, c4 = i & 31;
        float4 v = *(const float4*)&K[(size_t)k * 512 + c0 + c4 * 4];
        *(float4*)&Bs[k * 128 + c4 * 4] = v;
    }
    __syncthreads();

    const int ty = tid >> 5, tx = tid & 31;  // rows ty*8..+7, cols tx*4..+3
    float acc[8][4];
    #pragma unroll
    for (int i = 0; i < 8; i++)
        #pragma unroll
        for (int j = 0; j < 4; j++) acc[i][j] = 0.f;

    #pragma unroll 16
    for (int k = 0; k < 128; k++) {
        float4 a0 = *(float4*)&AsT[k * 68 + ty * 8];
        float4 a1 = *(float4*)&AsT[k * 68 + ty * 8 + 4];
        float4 bv = *(float4*)&Bs[k * 128 + tx * 4];
        float ar[8] = {a0.x, a0.y, a0.z, a0.w, a1.x, a1.y, a1.z, a1.w};
        float br[4] = {bv.x, bv.y, bv.z, bv.w};
        #pragma unroll
        for (int i = 0; i < 8; i++)
            #pragma unroll
            for (int j = 0; j < 4; j++) acc[i][j] += ar[i] * br[j];
    }

    float bb[4];
    #pragma unroll
    for (int j = 0; j < 4; j++) bb[j] = bl[c0 + tx * 4 + j];
    #pragma unroll
    for (int i = 0; i < 8; i++) {
        int row = bt0 + ty * 8 + i;
        float4 o;
        o.x = acc[i][0] + bb[0]; o.y = acc[i][1] + bb[1];
        o.z = acc[i][2] + bb[2]; o.w = acc[i][3] + bb[3];
        *(float4*)&g_gz[(size_t)row * 512 + c0 + tx * 4] = o;
    }
}

// ---------------------------------------------------------------------------
// LSTM recurrence. 128 blocks (2 batch rows each), 256 threads.
// smem: RhT[512][130] half (R transposed, padded) + h[2][128] half.
// Thread (r = tid>>7, k = tid&127) owns gate slot k of row r; c in register.
__global__ void k_lstm(const float* __restrict__ R) {
    extern __shared__ char smc[];
    half* RhT = (half*)smc;                       // 512*130 halves
    half* hsm = (half*)(smc + 512 * 130 * 2);     // 2*128 halves
    const int tid = threadIdx.x;
    const int b0 = blockIdx.x * 2;

    for (int i = tid; i < 128 * 512; i += 256) {
        int k2 = i >> 9, col = i & 511;
        RhT[col * 130 + k2] = __float2half(R[i]);
    }
    hsm[tid] = __float2half(0.f);
    __syncthreads();

    const int r = tid >> 7, k = tid & 127;
    const half2* hp = (const half2*)(hsm + r * 128);
    const half2* rI = (const half2*)(RhT + (size_t)(k)       * 130);
    const half2* rF = (const half2*)(RhT + (size_t)(k + 128) * 130);
    const half2* rG = (const half2*)(RhT + (size_t)(k + 256) * 130);
    const half2* rO = (const half2*)(RhT + (size_t)(k + 384) * 130);
    const float* gzp = g_gz + (size_t)(b0 + r) * T_ * 512 + k;
    float*       hsp = g_hs + (size_t)(b0 + r) * T_ * 128 + k;

    float c = 0.f;
    float gi = gzp[0], gf = gzp[128], gg = gzp[256], go = gzp[384];

    for (int t = 0; t < T_; t++) {
        // prefetch next-step gz while we compute the dot products
        float ni = 0.f, nf = 0.f, ng = 0.f, no = 0.f;
        if (t + 1 < T_) {
            const float* p = gzp + (size_t)(t + 1) * 512;
            ni = p[0]; nf = p[128]; ng = p[256]; no = p[384];
        }
        float fi = gi, ff = gf, fg = gg, fo = go;
        #pragma unroll
        for (int cc = 0; cc < 64; cc += 8) {   // 8 half2 = 16 k-terms per flush
            half2 z2 = __float2half2_rn(0.f);
            half2 aI = z2, aF = z2, aG = z2, aO = z2;
            #pragma unroll
            for (int j = 0; j < 8; j++) {
                half2 hv = hp[cc + j];
                aI = __hfma2(rI[cc + j], hv, aI);
                aF = __hfma2(rF[cc + j], hv, aF);
                aG = __hfma2(rG[cc + j], hv, aG);
                aO = __hfma2(rO[cc + j], hv, aO);
            }
            float2 v;
            v = __half22float2(aI); fi += v.x + v.y;
            v = __half22float2(aF); ff += v.x + v.y;
            v = __half22float2(aG); fg += v.x + v.y;
            v = __half22float2(aO); fo += v.x + v.y;
        }
        float ig  = sigmoidf_(fi);
        float fgt = sigmoidf_(ff);
        float gg2 = tanhf(fg);
        float og  = sigmoidf_(fo);
        c = fgt * c + ig * gg2;
        float hv = og * tanhf(c);

        __syncthreads();                    // all dot-reads of h done
        hsm[r * 128 + k] = __float2half(hv);
        hsp[(size_t)t * 128] = hv;
        __syncthreads();                    // new h visible

        gi = ni; gf = nf; gg = ng; go = no;
    }
}

// ---------------------------------------------------------------------------
// post_mean / post_scale = hs @ Wr_{m,s} (+bias, softplus on scale)
// grid 2048 (64 bt rows each), 256 threads.
__global__ void k_heads(const float* __restrict__ Wrm, const float* __restrict__ brm,
                        const float* __restrict__ Wrs, const float* __restrict__ brs) {
    extern __shared__ float sm[];
    float* AsT = sm;                 // [128][68]
    float* Wm  = sm + 128 * 68;      // [128][64]
    float* Ws  = Wm + 128 * 64;      // [128][64]
    const int tid = threadIdx.x;
    const int bt0 = blockIdx.x * 64;

    #pragma unroll
    for (int i = tid; i < 64 * 32; i += 256) {
        int row = i >> 5, c4 = i & 31;
        float4 v = *(const float4*)&g_hs[(size_t)(bt0 + row) * 128 + c4 * 4];
        AsT[(c4 * 4 + 0) * 68 + row] = v.x;
        AsT[(c4 * 4 + 1) * 68 + row] = v.y;
        AsT[(c4 * 4 + 2) * 68 + row] = v.z;
        AsT[(c4 * 4 + 3) * 68 + row] = v.w;
    }
    #pragma unroll
    for (int i = tid; i < 128 * 16; i += 256) {
        int k = i >> 4, c4 = i & 15;
        *(float4*)&Wm[k * 64 + c4 * 4] = *(const float4*)&Wrm[k * 64 + c4 * 4];
        *(float4*)&Ws[k * 64 + c4 * 4] = *(const float4*)&Wrs[k * 64 + c4 * 4];
    }
    __syncthreads();

    const int ty = tid >> 5, tx = tid & 31;   // rows ty*8..+7, cols tx*2..+1
    float am[8][2], as2[8][2];
    #pragma unroll
    for (int i = 0; i < 8; i++) { am[i][0]=am[i][1]=as2[i][0]=as2[i][1]=0.f; }

    #pragma unroll 16
    for (int k = 0; k < 128; k++) {
        float4 a0 = *(float4*)&AsT[k * 68 + ty * 8];
        float4 a1 = *(float4*)&AsT[k * 68 + ty * 8 + 4];
        float2 wm = *(float2*)&Wm[k * 64 + tx * 2];
        float2 ws = *(float2*)&Ws[k * 64 + tx * 2];
        float ar[8] = {a0.x, a0.y, a0.z, a0.w, a1.x, a1.y, a1.z, a1.w};
        #pragma unroll
        for (int i = 0; i < 8; i++) {
            am[i][0]  += ar[i] * wm.x;  am[i][1]  += ar[i] * wm.y;
            as2[i][0] += ar[i] * ws.x;  as2[i][1] += ar[i] * ws.y;
        }
    }

    float bm0 = brm[tx * 2], bm1 = brm[tx * 2 + 1];
    float bs0 = brs[tx * 2], bs1 = brs[tx * 2 + 1];
    #pragma unroll
    for (int i = 0; i < 8; i++) {
        size_t row = (size_t)(bt0 + ty * 8 + i);
        g_pm[row * 64 + tx * 2]     = am[i][0] + bm0;
        g_pm[row * 64 + tx * 2 + 1] = am[i][1] + bm1;
        g_ps[row * 64 + tx * 2]     = softplusf_(as2[i][0] + bs0);
        g_ps[row * 64 + tx * 2 + 1] = softplusf_(as2[i][1] + bs1);
    }
}

// ---------------------------------------------------------------------------
// generator + reconstruction term, reduced into g_acc[1].
// grid 4096 (32 bt rows each), 256 threads.
__global__ void k_gen(const float* __restrict__ obs, const float* __restrict__ Wgm,
                      const float* __restrict__ bgm, const float* __restrict__ Wgs,
                      const float* __restrict__ bgs) {
    extern __shared__ float sm[];
    float* AsT = sm;                 // [64][36]
    float* Wm  = sm + 64 * 36;       // [64][128]
    float* Ws  = Wm + 64 * 128;      // [64][128]
    __shared__ float red[8];
    const int tid = threadIdx.x;
    const int bt0 = blockIdx.x * 32;

    #pragma unroll
    for (int i = tid; i < 32 * 16; i += 256) {
        int row = i >> 4, c4 = i & 15;
        float4 v = *(const float4*)&g_pm[(size_t)(bt0 + row) * 64 + c4 * 4];
        AsT[(c4 * 4 + 0) * 36 + row] = v.x;
        AsT[(c4 * 4 + 1) * 36 + row] = v.y;
        AsT[(c4 * 4 + 2) * 36 + row] = v.z;
        AsT[(c4 * 4 + 3) * 36 + row] = v.w;
    }
    #pragma unroll
    for (int i = tid; i < 64 * 32; i += 256) {
        int k = i >> 5, c4 = i & 31;
        *(float4*)&Wm[k * 128 + c4 * 4] = *(const float4*)&Wgm[k * 128 + c4 * 4];
        *(float4*)&Ws[k * 128 + c4 * 4] = *(const float4*)&Wgs[k * 128 + c4 * 4];
    }
    __syncthreads();

    const int ty = tid >> 5, tx = tid & 31;   // rows ty*4..+3, cols tx*4..+3
    float am[4][4], asg[4][4];
    #pragma unroll
    for (int i = 0; i < 4; i++)
        #pragma unroll
        for (int j = 0; j < 4; j++) { am[i][j] = 0.f; asg[i][j] = 0.f; }

    #pragma unroll 16
    for (int k = 0; k < 64; k++) {
        float4 a  = *(float4*)&AsT[k * 36 + ty * 4];
        float4 wm = *(float4*)&Wm[k * 128 + tx * 4];
        float4 ws = *(float4*)&Ws[k * 128 + tx * 4];
        float ar[4]  = {a.x, a.y, a.z, a.w};
        float wmr[4] = {wm.x, wm.y, wm.z, wm.w};
        float wsr[4] = {ws.x, ws.y, ws.z, ws.w};
        #pragma unroll
        for (int i = 0; i < 4; i++)
            #pragma unroll
            for (int j = 0; j < 4; j++) {
                am[i][j]  += ar[i] * wmr[j];
                asg[i][j] += ar[i] * wsr[j];
            }
    }

    float bm[4], bs[4];
    #pragma unroll
    for (int j = 0; j < 4; j++) { bm[j] = bgm[tx * 4 + j]; bs[j] = bgs[tx * 4 + j]; }

    float lsum = 0.f;
    #pragma unroll
    for (int i = 0; i < 4; i++) {
        size_t row = (size_t)(bt0 + ty * 4 + i);
        float4 ov = *(const float4*)&obs[row * 128 + tx * 4];
        float orr[4] = {ov.x, ov.y, ov.z, ov.w};
        #pragma unroll
        for (int j = 0; j < 4; j++) {
            float mu = am[i][j] + bm[j];
            float sg = softplusf_(asg[i][j] + bs[j]);
            float d  = (orr[j] - mu) / sg;
            lsum += -0.5f * d * d - __logf(sg) - 0.91893853320467274f;
        }
    }
    #pragma unroll
    for (int off = 16; off; off >>= 1) lsum += __shfl_down_sync(0xffffffffu, lsum, off);
    if ((tid & 31) == 0) red[tid >> 5] = lsum;
    __syncthreads();
    if (tid == 0) {
        float s = 0.f;
        #pragma unroll
        for (int w = 0; w < 8; w++) s += red[w];
        atomicAdd(&g_acc[1], (double)s);
    }
}

// ---------------------------------------------------------------------------
// Prior rollout fused with the KL reduction. 256 blocks (one batch row), 64 thr.
__global__ void k_prior(const float* __restrict__ im, const float* __restrict__ Wfm,
                        const float* __restrict__ bfm, const float* __restrict__ Wfs,
                        const float* __restrict__ bfs) {
    __shared__ float Wm[64 * 64], Ws[64 * 64], msm[64];
    __shared__ float red[2];
    const int tid = threadIdx.x, b = blockIdx.x;

    for (int i = tid; i < 4096; i += 64) { Wm[i] = Wfm[i]; Ws[i] = Wfs[i]; }
    msm[tid] = im[b * 64 + tid];
    const float bm = bfm[tid], bsv = bfs[tid];
    __syncthreads();

    const float* pmrow = g_pm + (size_t)b * T_ * 64 + tid;
    const float* psrow = g_ps + (size_t)b * T_ * 64 + tid;

    float klsum = 0.f;
    for (int t = 0; t < T_; t++) {
        float amv = bm, asv = bsv;
        #pragma unroll 16
        for (int kk = 0; kk < 64; kk++) {
            float mv = msm[kk];
            amv += mv * Wm[kk * 64 + tid];
            asv += mv * Ws[kk * 64 + tid];
        }
        float sn = softplusf_(asv);
        float pm = pmrow[(size_t)t * 64];
        float ps = psrow[(size_t)t * 64];
        float d  = pm - amv;
        klsum += __logf(sn) - __logf(ps) + (ps * ps + d * d) / (2.f * sn * sn) - 0.5f;
        __syncthreads();
        msm[tid] = amv;
        __syncthreads();
    }
    #pragma unroll
    for (int off = 16; off; off >>= 1) klsum += __shfl_down_sync(0xffffffffu, klsum, off);
    if ((tid & 31) == 0) red[tid >> 5] = klsum;
    __syncthreads();
    if (tid == 0) atomicAdd(&g_acc[0], (double)(red[0] + red[1]));
}

// ---------------------------------------------------------------------------
__global__ void k_fin(float* out) {
    out[0] = (float)(g_acc[0] / (double)((size_t)B_ * T_) - g_acc[1] / (double)B_);
}

// ---------------------------------------------------------------------------
extern "C" void kernel_launch(void* const* d_in, const int* in_sizes, int n_in,
                              void* d_out, int out_size) {
    const float* obs = (const float*)d_in[0];
    const float* im  = (const float*)d_in[1];
    // d_in[2] = initial_scale (unused by the reference computation)
    const float* Wfm = (const float*)d_in[3];
    const float* bfm = (const float*)d_in[4];
    const float* Wfs = (const float*)d_in[5];
    const float* bfs = (const float*)d_in[6];
    const float* Wgm = (const float*)d_in[7];
    const float* bgm = (const float*)d_in[8];
    const float* Wgs = (const float*)d_in[9];
    const float* bgs = (const float*)d_in[10];
    const float* K   = (const float*)d_in[11];
    const float* R   = (const float*)d_in[12];
    const float* bl  = (const float*)d_in[13];
    const float* Wrm = (const float*)d_in[14];
    const float* brm = (const float*)d_in[15];
    const float* Wrs = (const float*)d_in[16];
    const float* brs = (const float*)d_in[17];
    float* out = (float*)d_out;

    const int XK_SM    = (128 * 68 + 128 * 128) * 4;            // 100352
    const int LSTM_SM  = 512 * 130 * 2 + 2 * 128 * 2;           // 133632
    const int HEADS_SM = (128 * 68 + 2 * 128 * 64) * 4;         // 100352
    const int GEN_SM   = (64 * 36 + 2 * 64 * 128) * 4;          // 74752

    cudaFuncSetAttribute(k_xk,    cudaFuncAttributeMaxDynamicSharedMemorySize, XK_SM);
    cudaFuncSetAttribute(k_lstm,  cudaFuncAttributeMaxDynamicSharedMemorySize, LSTM_SM);
    cudaFuncSetAttribute(k_heads, cudaFuncAttributeMaxDynamicSharedMemorySize, HEADS_SM);
    cudaFuncSetAttribute(k_gen,   cudaFuncAttributeMaxDynamicSharedMemorySize, GEN_SM);

    k_zero<<<1, 32>>>();
    k_xk<<<dim3(4, 2048), 256, XK_SM>>>(obs, K, bl);
    k_lstm<<<128, 256, LSTM_SM>>>(R);
    k_heads<<<2048, 256, HEADS_SM>>>(Wrm, brm, Wrs, brs);
    k_gen<<<4096, 256, GEN_SM>>>(obs, Wgm, bgm, Wgs, bgs);
    k_prior<<<256, 64>>>(im, Wfm, bfm, Wfs, bfs);
    k_fin<<<1, 1>>>(out);
}

// round 2
// speedup vs baseline: 4.1295x; 4.1295x over previous
#include <cuda_runtime.h>
#include <cuda_fp16.h>
#include <math.h>

#define B_  256
#define T_  512
#define S_  64
#define O_  128
#define H_  128
#define G4  512   // 4*H
#define BT_ ((size_t)B_ * T_)

// ---------------- scratch (device globals; no runtime allocation) ----------
__device__ __half g_obsh[BT_ * O_];        // 33.5 MB obs in half
__device__ float  g_gz  [BT_ * G4];        // 268 MB : obs@K + b (fp32)
__device__ __half g_hsh [BT_ * H_];        // 33.5 MB LSTM hidden (half)
__device__ __half g_pmh [BT_ * S_];        // 16.8 MB posterior mean (half)
__device__ float  g_ps  [BT_ * S_];        // 33.5 MB posterior scale (fp32)
__device__ __half g_KTh [512 * 128];       // K^T  (n-major)
__device__ __half g_WrTh[128 * 128];       // [Wrm|Wrs]^T (n-major, n<64 mean)
__device__ __half g_WgTh[256 * 64];        // [Wgm|Wgs]^T (n-major, n<128 mean)
__device__ double g_acc[2];                // [0]=KL sum, [1]=recon-logp sum

__device__ __forceinline__ float softplusf_(float x) {
    return fmaxf(x, 0.f) + __logf(1.f + __expf(-fabsf(x)));
}
__device__ __forceinline__ float sigmf_(float x) {
    return __fdividef(1.f, 1.f + __expf(-x));
}
__device__ __forceinline__ float tanhfast_(float x) {
    return __fdividef(2.f, 1.f + __expf(-2.f * x)) - 1.f;
}

__device__ __forceinline__ void mma16816(float* c, const unsigned* a, const unsigned* b) {
    asm volatile(
        "mma.sync.aligned.m16n8k16.row.col.f32.f16.f16.f32 "
        "{%0,%1,%2,%3}, {%4,%5,%6,%7}, {%8,%9}, {%0,%1,%2,%3};\n"
        : "+f"(c[0]), "+f"(c[1]), "+f"(c[2]), "+f"(c[3])
        : "r"(a[0]), "r"(a[1]), "r"(a[2]), "r"(a[3]), "r"(b[0]), "r"(b[1]));
}

// ---------------------------------------------------------------------------
__global__ void k_zero() { if (threadIdx.x < 2) g_acc[threadIdx.x] = 0.0; }

// obs -> half
__global__ void k_prep_obs(const float* __restrict__ obs) {
    size_t i = (size_t)blockIdx.x * blockDim.x + threadIdx.x;   // over n/4
    float4 v = ((const float4*)obs)[i];
    *(half2*)&g_obsh[i * 4]     = __floats2half2_rn(v.x, v.y);
    *(half2*)&g_obsh[i * 4 + 2] = __floats2half2_rn(v.z, v.w);
}

// weight transposes/concats -> half
__global__ void k_prep_w(const float* __restrict__ K,  const float* __restrict__ Wrm,
                         const float* __restrict__ Wrs, const float* __restrict__ Wgm,
                         const float* __restrict__ Wgs) {
    int stride = gridDim.x * blockDim.x;
    for (int i = blockIdx.x * blockDim.x + threadIdx.x; i < 98304; i += stride) {
        if (i < 65536) {
            int n = i >> 7, k = i & 127;
            g_KTh[i] = __float2half(K[k * 512 + n]);
        } else if (i < 81920) {
            int j = i - 65536; int n = j >> 7, k = j & 127;
            float v = (n < 64) ? Wrm[k * 64 + n] : Wrs[k * 64 + (n - 64)];
            g_WrTh[j] = __float2half(v);
        } else {
            int j = i - 81920; int n = j >> 6, k = j & 63;
            float v = (n < 128) ? Wgm[k * 128 + n] : Wgs[k * 128 + (n - 128)];
            g_WgTh[j] = __float2half(v);
        }
    }
}

// ---------------------------------------------------------------------------
// gz = obs @ K + b via HMMA.  grid (4, 1024), 256 thr.  tile 128x128, k=128.
__global__ __launch_bounds__(256) void k_xk(const float* __restrict__ bl) {
    extern __shared__ __half sm[];
    __half* As = sm;                 // [128][136]
    __half* Bt = sm + 128 * 136;     // [128][136]  (K^T tile: [n][k])
    const int tid = threadIdx.x;
    const int bt0 = blockIdx.y * 128;
    const int c0  = blockIdx.x * 128;

    const uint4* ap = (const uint4*)(g_obsh + (size_t)bt0 * 128);
    const uint4* bp = (const uint4*)(g_KTh  + (size_t)c0  * 128);
    #pragma unroll
    for (int i = tid; i < 128 * 16; i += 256) {
        int r = i >> 4, c = i & 15;
        *(uint4*)&As[r * 136 + c * 8] = ap[r * 16 + c];
        *(uint4*)&Bt[r * 136 + c * 8] = bp[r * 16 + c];
    }
    __syncthreads();

    const int w = tid >> 5, l = tid & 31, g = l >> 2, tg = l & 3;
    const int m0 = w * 16;
    float acc[16][4];
    #pragma unroll
    for (int i = 0; i < 16; i++)
        #pragma unroll
        for (int j = 0; j < 4; j++) acc[i][j] = 0.f;

    #pragma unroll
    for (int kk = 0; kk < 8; kk++) {
        const int kb = kk * 16 + tg * 2;
        unsigned a[4];
        a[0] = *(const unsigned*)&As[(m0 + g)     * 136 + kb];
        a[1] = *(const unsigned*)&As[(m0 + g + 8) * 136 + kb];
        a[2] = *(const unsigned*)&As[(m0 + g)     * 136 + kb + 8];
        a[3] = *(const unsigned*)&As[(m0 + g + 8) * 136 + kb + 8];
        #pragma unroll
        for (int na = 0; na < 16; na++) {
            unsigned b[2];
            b[0] = *(const unsigned*)&Bt[(na * 8 + g) * 136 + kb];
            b[1] = *(const unsigned*)&Bt[(na * 8 + g) * 136 + kb + 8];
            mma16816(acc[na], a, b);
        }
    }
    #pragma unroll
    for (int na = 0; na < 16; na++) {
        int cc = c0 + na * 8 + tg * 2;
        float2 bb = *(const float2*)&bl[cc];
        size_t r0 = (size_t)(bt0 + m0 + g) * 512 + cc;
        *(float2*)&g_gz[r0]            = make_float2(acc[na][0] + bb.x, acc[na][1] + bb.y);
        *(float2*)&g_gz[r0 + 8 * 512]  = make_float2(acc[na][2] + bb.x, acc[na][3] + bb.y);
    }
}

// ---------------------------------------------------------------------------
// LSTM recurrence: 128 blocks x 512 thr. Weights in registers (half2),
// h broadcast from smem, gate recombine via smem exchange.
__global__ __launch_bounds__(512, 1) void k_lstm(const float* __restrict__ R) {
    __shared__ __half hh[2 * 128];
    __shared__ float  zbuf[2 * 512];
    const int tid = threadIdx.x;
    const int b0  = blockIdx.x * 2;

    half2 wreg[64];
    #pragma unroll
    for (int j = 0; j < 64; j++)
        wreg[j] = __floats2half2_rn(R[(size_t)(2 * j) * 512 + tid],
                                    R[(size_t)(2 * j + 1) * 512 + tid]);
    if (tid < 256) hh[tid] = __float2half(0.f);

    const float* gz0 = g_gz + (size_t)b0 * T_ * 512 + tid;
    const float* gz1 = gz0 + (size_t)T_ * 512;
    const int r_ = tid >> 7, k_ = tid & 127;         // combine role (tid<256)
    __half* hout = g_hsh + (size_t)(b0 + r_) * T_ * 128 + k_;
    float cst = 0.f;

    float gv0 = gz0[0], gv1 = gz1[0];
    __syncthreads();

    for (int t = 0; t < T_; t++) {
        float ngv0 = 0.f, ngv1 = 0.f;
        if (t + 1 < T_) {
            ngv0 = gz0[(size_t)(t + 1) * 512];
            ngv1 = gz1[(size_t)(t + 1) * 512];
        }
        float fs[2] = {gv0, gv1};
        #pragma unroll
        for (int r = 0; r < 2; r++) {
            const uint4* hq = (const uint4*)(hh + r * 128);
            float acc = 0.f;
            #pragma unroll
            for (int cb = 0; cb < 4; cb++) {          // 4 chunks x 32 terms
                uint4 q0 = hq[cb * 4 + 0], q1 = hq[cb * 4 + 1];
                uint4 q2 = hq[cb * 4 + 2], q3 = hq[cb * 4 + 3];
                const half2* x0 = (const half2*)&q0;
                const half2* x1 = (const half2*)&q1;
                const half2* x2 = (const half2*)&q2;
                const half2* x3 = (const half2*)&q3;
                half2 a2 = __float2half2_rn(0.f);
                #pragma unroll
                for (int j = 0; j < 4; j++) a2 = __hfma2(wreg[cb * 16 + j],      x0[j], a2);
                #pragma unroll
                for (int j = 0; j < 4; j++) a2 = __hfma2(wreg[cb * 16 + 4 + j],  x1[j], a2);
                #pragma unroll
                for (int j = 0; j < 4; j++) a2 = __hfma2(wreg[cb * 16 + 8 + j],  x2[j], a2);
                #pragma unroll
                for (int j = 0; j < 4; j++) a2 = __hfma2(wreg[cb * 16 + 12 + j], x3[j], a2);
                float2 v = __half22float2(a2);
                acc += v.x + v.y;
            }
            fs[r] += acc;
        }
        zbuf[tid]       = fs[0];
        zbuf[512 + tid] = fs[1];
        __syncthreads();
        if (tid < 256) {
            const float* zb = zbuf + r_ * 512;
            float ig = sigmf_(zb[k_]);
            float fg = sigmf_(zb[128 + k_]);
            float gg = tanhfast_(zb[256 + k_]);
            float og = sigmf_(zb[384 + k_]);
            cst = fg * cst + ig * gg;
            float hv = og * tanhfast_(cst);
            __half hh16 = __float2half(hv);
            hh[r_ * 128 + k_] = hh16;
            hout[(size_t)t * 128] = hh16;
        }
        __syncthreads();
        gv0 = ngv0; gv1 = ngv1;
    }
}

// ---------------------------------------------------------------------------
// heads: [hs]@[Wrm|Wrs] via HMMA.  grid 1024, 256 thr.  tile 128x128, k=128.
__global__ __launch_bounds__(256) void k_heads(const float* __restrict__ brm,
                                               const float* __restrict__ brs) {
    extern __shared__ __half sm[];
    __half* As = sm;                 // [128][136]
    __half* Bt = sm + 128 * 136;     // [128][136]
    const int tid = threadIdx.x;
    const int bt0 = blockIdx.x * 128;

    const uint4* ap = (const uint4*)(g_hsh + (size_t)bt0 * 128);
    const uint4* bp = (const uint4*)g_WrTh;
    #pragma unroll
    for (int i = tid; i < 128 * 16; i += 256) {
        int r = i >> 4, c = i & 15;
        *(uint4*)&As[r * 136 + c * 8] = ap[r * 16 + c];
        *(uint4*)&Bt[r * 136 + c * 8] = bp[r * 16 + c];
    }
    __syncthreads();

    const int w = tid >> 5, l = tid & 31, g = l >> 2, tg = l & 3;
    const int m0 = w * 16;
    float acc[16][4];
    #pragma unroll
    for (int i = 0; i < 16; i++)
        #pragma unroll
        for (int j = 0; j < 4; j++) acc[i][j] = 0.f;

    #pragma unroll
    for (int kk = 0; kk < 8; kk++) {
        const int kb = kk * 16 + tg * 2;
        unsigned a[4];
        a[0] = *(const unsigned*)&As[(m0 + g)     * 136 + kb];
        a[1] = *(const unsigned*)&As[(m0 + g + 8) * 136 + kb];
        a[2] = *(const unsigned*)&As[(m0 + g)     * 136 + kb + 8];
        a[3] = *(const unsigned*)&As[(m0 + g + 8) * 136 + kb + 8];
        #pragma unroll
        for (int na = 0; na < 16; na++) {
            unsigned b[2];
            b[0] = *(const unsigned*)&Bt[(na * 8 + g) * 136 + kb];
            b[1] = *(const unsigned*)&Bt[(na * 8 + g) * 136 + kb + 8];
            mma16816(acc[na], a, b);
        }
    }
    #pragma unroll
    for (int na = 0; na < 16; na++) {
        int cc = na * 8 + tg * 2;                 // 0..127 within concat
        int r0 = bt0 + m0 + g, r1 = r0 + 8;
        if (cc < 64) {
            float2 bm = *(const float2*)&brm[cc];
            *(half2*)&g_pmh[(size_t)r0 * 64 + cc] =
                __floats2half2_rn(acc[na][0] + bm.x, acc[na][1] + bm.y);
            *(half2*)&g_pmh[(size_t)r1 * 64 + cc] =
                __floats2half2_rn(acc[na][2] + bm.x, acc[na][3] + bm.y);
        } else {
            int c2 = cc - 64;
            float2 bs = *(const float2*)&brs[c2];
            *(float2*)&g_ps[(size_t)r0 * 64 + c2] =
                make_float2(softplusf_(acc[na][0] + bs.x), softplusf_(acc[na][1] + bs.y));
            *(float2*)&g_ps[(size_t)r1 * 64 + c2] =
                make_float2(softplusf_(acc[na][2] + bs.x), softplusf_(acc[na][3] + bs.y));
        }
    }
}

// ---------------------------------------------------------------------------
// generator + recon term via HMMA, fused reduction.  grid 1024, 512 thr.
// tile 128 rows x 256 cols ([Wgm|Wgs]), k=64.
__global__ __launch_bounds__(512) void k_gen(const float* __restrict__ obs,
                                             const float* __restrict__ bgm,
                                             const float* __restrict__ bgs) {
    extern __shared__ __half sm[];
    __half* As = sm;                 // [128][72]
    __half* Bt = sm + 128 * 72;      // [256][72]
    __shared__ float red[16];
    const int tid = threadIdx.x;
    const int bt0 = blockIdx.x * 128;

    const uint4* ap = (const uint4*)(g_pmh + (size_t)bt0 * 64);
    #pragma unroll
    for (int i = tid; i < 128 * 8; i += 512) {
        int r = i >> 3, c = i & 7;
        *(uint4*)&As[r * 72 + c * 8] = ap[r * 8 + c];
    }
    const uint4* bp = (const uint4*)g_WgTh;
    #pragma unroll
    for (int i = tid; i < 256 * 8; i += 512) {
        int r = i >> 3, c = i & 7;
        *(uint4*)&Bt[r * 72 + c * 8] = bp[i];
    }
    __syncthreads();

    const int w = tid >> 5, l = tid & 31, g = l >> 2, tg = l & 3;
    const int strip = w >> 1, ch = w & 1;
    const int m0 = strip * 16;
    float am[8][4], as_[8][4];
    #pragma unroll
    for (int i = 0; i < 8; i++)
        #pragma unroll
        for (int j = 0; j < 4; j++) { am[i][j] = 0.f; as_[i][j] = 0.f; }

    #pragma unroll
    for (int kk = 0; kk < 4; kk++) {
        const int kb = kk * 16 + tg * 2;
        unsigned a[4];
        a[0] = *(const unsigned*)&As[(m0 + g)     * 72 + kb];
        a[1] = *(const unsigned*)&As[(m0 + g + 8) * 72 + kb];
        a[2] = *(const unsigned*)&As[(m0 + g)     * 72 + kb + 8];
        a[3] = *(const unsigned*)&As[(m0 + g + 8) * 72 + kb + 8];
        #pragma unroll
        for (int na = 0; na < 8; na++) {
            int nmu = ch * 64 + na * 8 + g;
            unsigned b[2], b2[2];
            b[0]  = *(const unsigned*)&Bt[nmu * 72 + kb];
            b[1]  = *(const unsigned*)&Bt[nmu * 72 + kb + 8];
            b2[0] = *(const unsigned*)&Bt[(nmu + 128) * 72 + kb];
            b2[1] = *(const unsigned*)&Bt[(nmu + 128) * 72 + kb + 8];
            mma16816(am[na], a, b);
            mma16816(as_[na], a, b2);
        }
    }

    float lsum = 0.f;
    #pragma unroll
    for (int na = 0; na < 8; na++) {
        int oc = ch * 64 + na * 8 + tg * 2;
        float2 bm2 = *(const float2*)&bgm[oc];
        float2 bs2 = *(const float2*)&bgs[oc];
        int r0 = bt0 + m0 + g, r1 = r0 + 8;
        float2 o0 = *(const float2*)&obs[(size_t)r0 * 128 + oc];
        float2 o1 = *(const float2*)&obs[(size_t)r1 * 128 + oc];
        float mu, sg, d;
        mu = am[na][0] + bm2.x; sg = softplusf_(as_[na][0] + bs2.x);
        d = __fdividef(o0.x - mu, sg); lsum += -0.5f * d * d - __logf(sg);
        mu = am[na][1] + bm2.y; sg = softplusf_(as_[na][1] + bs2.y);
        d = __fdividef(o0.y - mu, sg); lsum += -0.5f * d * d - __logf(sg);
        mu = am[na][2] + bm2.x; sg = softplusf_(as_[na][2] + bs2.x);
        d = __fdividef(o1.x - mu, sg); lsum += -0.5f * d * d - __logf(sg);
        mu = am[na][3] + bm2.y; sg = softplusf_(as_[na][3] + bs2.y);
        d = __fdividef(o1.y - mu, sg); lsum += -0.5f * d * d - __logf(sg);
    }
    lsum -= 32.f * 0.91893853320467274f;   // 32 elements x 0.5*log(2pi)

    #pragma unroll
    for (int off = 16; off; off >>= 1) lsum += __shfl_down_sync(0xffffffffu, lsum, off);
    if (l == 0) red[w] = lsum;
    __syncthreads();
    if (tid == 0) {
        float s = 0.f;
        #pragma unroll
        for (int i = 0; i < 16; i++) s += red[i];
        atomicAdd(&g_acc[1], (double)s);
    }
}

// ---------------------------------------------------------------------------
// Prior rollout + KL. 256 blocks x 64 thr. Weights in half2 registers.
__global__ __launch_bounds__(64) void k_prior(const float* __restrict__ im,
                                              const float* __restrict__ Wfm,
                                              const float* __restrict__ bfm,
                                              const float* __restrict__ Wfs,
                                              const float* __restrict__ bfs) {
    __shared__ __half mh[64];
    __shared__ float red[2];
    const int s = threadIdx.x, b = blockIdx.x;

    half2 wm[32], ws[32];
    #pragma unroll
    for (int j = 0; j < 32; j++) {
        wm[j] = __floats2half2_rn(Wfm[(2 * j) * 64 + s], Wfm[(2 * j + 1) * 64 + s]);
        ws[j] = __floats2half2_rn(Wfs[(2 * j) * 64 + s], Wfs[(2 * j + 1) * 64 + s]);
    }
    mh[s] = __float2half(im[b * 64 + s]);
    const float bmv = bfm[s], bsv = bfs[s];
    __syncthreads();

    const __half* pmp = g_pmh + (size_t)b * T_ * 64 + s;
    const float*  psp = g_ps  + (size_t)b * T_ * 64 + s;
    float pmv = __half2float(pmp[0]);
    float psv = psp[0];

    float klsum = 0.f;
    for (int t = 0; t < T_; t++) {
        float npm = 0.f, nps = 1.f;
        if (t + 1 < T_) {
            npm = __half2float(pmp[(size_t)(t + 1) * 64]);
            nps = psp[(size_t)(t + 1) * 64];
        }
        float amv = bmv, asv = bsv;
        const uint4* m4 = (const uint4*)mh;
        #pragma unroll
        for (int cb = 0; cb < 2; cb++) {         // 2 chunks x 32 terms
            uint4 q0 = m4[cb * 4 + 0], q1 = m4[cb * 4 + 1];
            uint4 q2 = m4[cb * 4 + 2], q3 = m4[cb * 4 + 3];
            const half2* x0 = (const half2*)&q0;
            const half2* x1 = (const half2*)&q1;
            const half2* x2 = (const half2*)&q2;
            const half2* x3 = (const half2*)&q3;
            half2 am2 = __float2half2_rn(0.f), as2 = am2;
            #pragma unroll
            for (int j = 0; j < 4; j++) {
                am2 = __hfma2(wm[cb * 16 + j],      x0[j], am2);
                as2 = __hfma2(ws[cb * 16 + j],      x0[j], as2);
                am2 = __hfma2(wm[cb * 16 + 4 + j],  x1[j], am2);
                as2 = __hfma2(ws[cb * 16 + 4 + j],  x1[j], as2);
                am2 = __hfma2(wm[cb * 16 + 8 + j],  x2[j], am2);
                as2 = __hfma2(ws[cb * 16 + 8 + j],  x2[j], as2);
                am2 = __hfma2(wm[cb * 16 + 12 + j], x3[j], am2);
                as2 = __hfma2(ws[cb * 16 + 12 + j], x3[j], as2);
            }
            float2 v;
            v = __half22float2(am2); amv += v.x + v.y;
            v = __half22float2(as2); asv += v.x + v.y;
        }
        float sn = softplusf_(asv);
        float d  = pmv - amv;
        klsum += __logf(__fdividef(sn, psv))
               + __fdividef(psv * psv + d * d, 2.f * sn * sn) - 0.5f;
        __syncthreads();
        mh[s] = __float2half(amv);
        __syncthreads();
        pmv = npm; psv = nps;
    }
    #pragma unroll
    for (int off = 16; off; off >>= 1) klsum += __shfl_down_sync(0xffffffffu, klsum, off);
    if ((s & 31) == 0) red[s >> 5] = klsum;
    __syncthreads();
    if (s == 0) atomicAdd(&g_acc[0], (double)(red[0] + red[1]));
}

// ---------------------------------------------------------------------------
__global__ void k_fin(float* out) {
    out[0] = (float)(g_acc[0] / (double)BT_ - g_acc[1] / (double)B_);
}

// ---------------------------------------------------------------------------
extern "C" void kernel_launch(void* const* d_in, const int* in_sizes, int n_in,
                              void* d_out, int out_size) {
    const float* obs = (const float*)d_in[0];
    const float* im  = (const float*)d_in[1];
    // d_in[2] = initial_scale (unused by the reference computation)
    const float* Wfm = (const float*)d_in[3];
    const float* bfm = (const float*)d_in[4];
    const float* Wfs = (const float*)d_in[5];
    const float* bfs = (const float*)d_in[6];
    const float* Wgm = (const float*)d_in[7];
    const float* bgm = (const float*)d_in[8];
    const float* Wgs = (const float*)d_in[9];
    const float* bgs = (const float*)d_in[10];
    const float* K   = (const float*)d_in[11];
    const float* R   = (const float*)d_in[12];
    const float* bl  = (const float*)d_in[13];
    const float* Wrm = (const float*)d_in[14];
    const float* brm = (const float*)d_in[15];
    const float* Wrs = (const float*)d_in[16];
    const float* brs = (const float*)d_in[17];
    float* out = (float*)d_out;

    const int GEMM_SM = 2 * 128 * 136 * 2;          // 69632
    const int GEN_SM  = (128 * 72 + 256 * 72) * 2;  // 55296
    cudaFuncSetAttribute(k_xk,    cudaFuncAttributeMaxDynamicSharedMemorySize, GEMM_SM);
    cudaFuncSetAttribute(k_heads, cudaFuncAttributeMaxDynamicSharedMemorySize, GEMM_SM);
    cudaFuncSetAttribute(k_gen,   cudaFuncAttributeMaxDynamicSharedMemorySize, GEN_SM);

    k_zero<<<1, 32>>>();
    k_prep_obs<<<16384, 256>>>(obs);
    k_prep_w<<<128, 256>>>(K, Wrm, Wrs, Wgm, Wgs);
    k_xk<<<dim3(4, 1024), 256, GEMM_SM>>>(bl);
    k_lstm<<<128, 512>>>(R);
    k_heads<<<1024, 256, GEMM_SM>>>(brm, brs);
    k_gen<<<1024, 512, GEN_SM>>>(obs, bgm, bgs);
    k_prior<<<256, 64>>>(im, Wfm, bfm, Wfs, bfs);
    k_fin<<<1, 1>>>(out);
}